// round 3
// baseline (speedup 1.0000x reference)
#include <cuda_runtime.h>
#include <cuda_bf16.h>

// Problem constants
#define T_TOK   32768
#define B_SEG   8
#define H_HEAD  8
#define D_DIM   128
#define HD      (H_HEAD * D_DIM)   // 1024 floats per token row

// Scratch (device globals — no allocation allowed)
__device__ float g_sums[B_SEG * D_DIM];     // segment+head sums (8 x 128)
__device__ float g_h1[B_SEG * 1024];        // layer1 out
__device__ float g_h2[B_SEG * 256];         // layer2 out (atomic target)
__device__ float g_h3[B_SEG * 512];         // layer3 out
__device__ float g_h4[B_SEG * 128];         // layer4 out (atomic target, pre-silu)

__device__ __forceinline__ float silu_f(float x) {
    return x / (1.0f + __expf(-x));
}

// ---------------------------------------------------------------------------
// K0: zero the buffers that get atomically accumulated
// ---------------------------------------------------------------------------
__global__ void zero_kernel() {
    int i = blockIdx.x * blockDim.x + threadIdx.x;
    if (i < B_SEG * D_DIM) g_sums[i] = 0.0f;
    if (i < B_SEG * 256)   g_h2[i]   = 0.0f;
    if (i < B_SEG * 128)   g_h4[i]   = 0.0f;
}

// ---------------------------------------------------------------------------
// K1: segment + head sum.  x is (T, H, D) fp32; we produce
//     g_sums[b][d] = sum over tokens t in segment b, sum over h of x[t,h,d].
// 1024 blocks x 256 threads; each block owns 32 contiguous token rows (128 KB).
// Each thread loads one float4 per token (d-range = (4*tid) & 127 .. +3).
// ---------------------------------------------------------------------------
#define SEG_BLOCKS 1024
#define TOKS_PER_BLK (T_TOK / SEG_BLOCKS)   // 32

__global__ __launch_bounds__(256) void segsum_kernel(
    const float4* __restrict__ x, const int* __restrict__ cu)
{
    __shared__ float ssum[B_SEG * D_DIM];
    __shared__ int   touched[B_SEG];

    const int tid = threadIdx.x;
    for (int i = tid; i < B_SEG * D_DIM; i += 256) ssum[i] = 0.0f;
    if (tid < B_SEG) touched[tid] = 0;
    __syncthreads();

    // cu_seq_len inner boundaries (cu[0]=0, cu[8]=T)
    const int c1 = cu[1], c2 = cu[2], c3 = cu[3], c4 = cu[4];
    const int c5 = cu[5], c6 = cu[6], c7 = cu[7];

    const int t0    = blockIdx.x * TOKS_PER_BLK;
    const int dbase = (4 * tid) & (D_DIM - 1);   // 4 consecutive d's, no wrap

    float a0 = 0.f, a1 = 0.f, a2 = 0.f, a3 = 0.f;
    int curseg = -1;

    #pragma unroll 4
    for (int tt = 0; tt < TOKS_PER_BLK; tt++) {
        const int t = t0 + tt;
        // seg = number of boundaries <= t  (matches searchsorted 'right' - 1,
        // including the duplicate-boundary / empty-segment case)
        int seg = (t >= c1) + (t >= c2) + (t >= c3) + (t >= c4)
                + (t >= c5) + (t >= c6) + (t >= c7);
        if (seg != curseg) {               // block-uniform branch
            if (curseg >= 0) {
                atomicAdd(&ssum[curseg * D_DIM + dbase + 0], a0);
                atomicAdd(&ssum[curseg * D_DIM + dbase + 1], a1);
                atomicAdd(&ssum[curseg * D_DIM + dbase + 2], a2);
                atomicAdd(&ssum[curseg * D_DIM + dbase + 3], a3);
                touched[curseg] = 1;
            }
            curseg = seg;
            a0 = a1 = a2 = a3 = 0.f;
        }
        float4 v = x[(size_t)t * (HD / 4) + tid];
        a0 += v.x; a1 += v.y; a2 += v.z; a3 += v.w;
    }
    if (curseg >= 0) {
        atomicAdd(&ssum[curseg * D_DIM + dbase + 0], a0);
        atomicAdd(&ssum[curseg * D_DIM + dbase + 1], a1);
        atomicAdd(&ssum[curseg * D_DIM + dbase + 2], a2);
        atomicAdd(&ssum[curseg * D_DIM + dbase + 3], a3);
        touched[curseg] = 1;
    }
    __syncthreads();

    for (int s = 0; s < B_SEG; s++) {
        if (touched[s]) {
            for (int i = tid; i < D_DIM; i += 256)
                atomicAdd(&g_sums[s * D_DIM + i], ssum[s * D_DIM + i]);
        }
    }
}

// ---------------------------------------------------------------------------
// Generic tiny-batch (B=8) dense layer:  out[b][j] = act( in[b][:]·w[:,j] + bias[j] )
//   - w is (K, N) row-major (JAX layout)
//   - grid.x tiles N (128 threads/block, one output column each)
//   - grid.y tiles K in KCHUNK slices (split-K with atomicAdd when >1)
//   - SCALE_IN: in = g_sums scaled by 1/(8*max(count,1))  (pooling divide)
//   - SILU_IN:  apply silu while loading input (deferred from previous layer)
// ---------------------------------------------------------------------------
template<int K, int N, int KCHUNK, bool SCALE_IN, bool SILU_IN, bool SILU_OUT, bool ATOMIC>
__device__ __forceinline__ void mlp_body(
    const float* __restrict__ in, const float* __restrict__ w,
    const float* __restrict__ bias, float* out, const int* __restrict__ cu)
{
    __shared__ float s_in[B_SEG * KCHUNK];
    const int tid   = threadIdx.x;
    const int kbase = blockIdx.y * KCHUNK;

    for (int i = tid; i < B_SEG * KCHUNK; i += blockDim.x) {
        const int b = i / KCHUNK;
        const int k = i - b * KCHUNK;
        float v = in[b * K + kbase + k];
        if (SCALE_IN) {
            int cnt = cu[b + 1] - cu[b];
            float c = (float)(cnt > 1 ? cnt : 1);
            v *= 1.0f / (8.0f * c);
        }
        if (SILU_IN) v = silu_f(v);
        s_in[i] = v;
    }
    __syncthreads();

    const int j = blockIdx.x * blockDim.x + tid;
    if (j < N) {
        float acc[B_SEG];
        const float binit = (blockIdx.y == 0) ? bias[j] : 0.0f;
        #pragma unroll
        for (int b = 0; b < B_SEG; b++) acc[b] = binit;

        for (int k = 0; k < KCHUNK; k++) {
            const float wv = w[(size_t)(kbase + k) * N + j];
            #pragma unroll
            for (int b = 0; b < B_SEG; b++)
                acc[b] += s_in[b * KCHUNK + k] * wv;
        }

        #pragma unroll
        for (int b = 0; b < B_SEG; b++) {
            if (ATOMIC) {
                atomicAdd(&out[b * N + j], acc[b]);
            } else {
                float v = acc[b];
                if (SILU_OUT) v = silu_f(v);
                out[b * N + j] = v;
            }
        }
    }
}

// L1: pooled(128) -> 1024, silu.  in = g_sums with pooling scale.
__global__ __launch_bounds__(128) void l1_kernel(
    const float* __restrict__ w, const float* __restrict__ b, const int* __restrict__ cu) {
    mlp_body<128, 1024, 128, true, false, true, false>(g_sums, w, b, g_h1, cu);
}
// L2: 1024 -> 256, no act.  split-K (8 chunks of 128), atomic.
__global__ __launch_bounds__(128) void l2_kernel(
    const float* __restrict__ w, const float* __restrict__ b) {
    mlp_body<1024, 256, 128, false, false, false, true>(g_h1, w, b, g_h2, nullptr);
}
// L3: 256 -> 512, silu.
__global__ __launch_bounds__(128) void l3_kernel(
    const float* __restrict__ w, const float* __restrict__ b) {
    mlp_body<256, 512, 256, false, false, true, false>(g_h2, w, b, g_h3, nullptr);
}
// L4: 512 -> 128, split-K (4 chunks), atomic, silu DEFERRED to L5's input load.
__global__ __launch_bounds__(128) void l4_kernel(
    const float* __restrict__ w, const float* __restrict__ b) {
    mlp_body<512, 128, 128, false, false, false, true>(g_h3, w, b, g_h4, nullptr);
}

// ---------------------------------------------------------------------------
// L5: logits = silu(h4) @ w5 + b5  (K=128, N=2), then
//     z[b] = (logit1 > logit0) ? 1 : 0   (argmax tie -> class 0 -> z = 0)
//     out is (B, H, 1) = 64 floats, z broadcast over H.
// ---------------------------------------------------------------------------
__global__ __launch_bounds__(128) void l5_kernel(
    const float* __restrict__ w5, const float* __restrict__ b5, float* __restrict__ out)
{
    __shared__ float r0[128], r1[128];
    const int k = threadIdx.x;
    const float w0 = w5[k * 2 + 0];
    const float w1 = w5[k * 2 + 1];

    for (int b = 0; b < B_SEG; b++) {
        float s = silu_f(g_h4[b * 128 + k]);
        r0[k] = s * w0;
        r1[k] = s * w1;
        __syncthreads();
        for (int off = 64; off >= 1; off >>= 1) {
            if (k < off) { r0[k] += r0[k + off]; r1[k] += r1[k + off]; }
            __syncthreads();
        }
        if (k == 0) {
            const float l0 = r0[0] + b5[0];
            const float l1 = r1[0] + b5[1];
            const float z  = (l1 > l0) ? 1.0f : 0.0f;
            #pragma unroll
            for (int h = 0; h < H_HEAD; h++) out[b * H_HEAD + h] = z;
        }
        __syncthreads();
    }
}

// ---------------------------------------------------------------------------
// Launch
// ---------------------------------------------------------------------------
extern "C" void kernel_launch(void* const* d_in, const int* in_sizes, int n_in,
                              void* d_out, int out_size)
{
    const float* x  = (const float*)d_in[0];
    const int*   cu = (const int*)  d_in[1];
    const float* w1 = (const float*)d_in[2];
    const float* b1 = (const float*)d_in[3];
    const float* w2 = (const float*)d_in[4];
    const float* b2 = (const float*)d_in[5];
    const float* w3 = (const float*)d_in[6];
    const float* b3 = (const float*)d_in[7];
    const float* w4 = (const float*)d_in[8];
    const float* b4 = (const float*)d_in[9];
    const float* w5 = (const float*)d_in[10];
    const float* b5 = (const float*)d_in[11];
    float* out = (float*)d_out;

    zero_kernel<<<8, 256>>>();
    segsum_kernel<<<SEG_BLOCKS, 256>>>((const float4*)x, cu);
    l1_kernel<<<dim3(1024 / 128, 1), 128>>>(w1, b1, cu);
    l2_kernel<<<dim3(256 / 128, 1024 / 128), 128>>>(w2, b2);
    l3_kernel<<<dim3(512 / 128, 1), 128>>>(w3, b3);
    l4_kernel<<<dim3(1, 512 / 128), 128>>>(w4, b4);
    l5_kernel<<<1, 128>>>(w5, b5, out);
}

// round 4
// speedup vs baseline: 1.7022x; 1.7022x over previous
#include <cuda_runtime.h>
#include <cuda_bf16.h>

// Problem constants
#define T_TOK   32768
#define B_SEG   8
#define H_HEAD  8
#define D_DIM   128
#define HD      (H_HEAD * D_DIM)   // 1024 floats per token row
#define NB      16                 // blocks in fused MLP kernel

// Scratch (device globals — no allocation allowed)
__device__ float    g_sums[B_SEG * D_DIM];       // segment+head sums (8 x 128)
__device__ float    g_h1[B_SEG * 1024];          // L1 out (silu applied)
__device__ float    g_p2[NB * B_SEG * 256];      // L2 split-K partials
__device__ float    g_h3[B_SEG * 512];           // L3 out (silu applied)
__device__ float    g_p4[NB * B_SEG * 128];      // L4 split-K partials
__device__ unsigned g_bar[4];                    // grid barrier counters

__device__ __forceinline__ float silu_f(float x) {
    return x / (1.0f + __expf(-x));
}

// ---------------------------------------------------------------------------
// K0: zero the atomic target + barrier counters (runs each graph replay)
// ---------------------------------------------------------------------------
__global__ void zero_kernel() {
    int i = blockIdx.x * blockDim.x + threadIdx.x;
    if (i < B_SEG * D_DIM) g_sums[i] = 0.0f;
    if (i < 4)             g_bar[i]  = 0u;
}

// ---------------------------------------------------------------------------
// K1: segment + head sum.  g_sums[b][d] = sum_{t in seg b} sum_h x[t,h,d]
// 1024 blocks x 256 threads; block owns 32 contiguous token rows (128 KB).
// ---------------------------------------------------------------------------
#define SEG_BLOCKS 1024
#define TOKS_PER_BLK (T_TOK / SEG_BLOCKS)   // 32

__global__ __launch_bounds__(256) void segsum_kernel(
    const float4* __restrict__ x, const int* __restrict__ cu)
{
    __shared__ float ssum[B_SEG * D_DIM];
    __shared__ int   touched[B_SEG];

    const int tid = threadIdx.x;
    for (int i = tid; i < B_SEG * D_DIM; i += 256) ssum[i] = 0.0f;
    if (tid < B_SEG) touched[tid] = 0;
    __syncthreads();

    const int c1 = cu[1], c2 = cu[2], c3 = cu[3], c4 = cu[4];
    const int c5 = cu[5], c6 = cu[6], c7 = cu[7];

    const int t0    = blockIdx.x * TOKS_PER_BLK;
    const int dbase = (4 * tid) & (D_DIM - 1);

    float a0 = 0.f, a1 = 0.f, a2 = 0.f, a3 = 0.f;
    int curseg = -1;

    #pragma unroll 4
    for (int tt = 0; tt < TOKS_PER_BLK; tt++) {
        const int t = t0 + tt;
        int seg = (t >= c1) + (t >= c2) + (t >= c3) + (t >= c4)
                + (t >= c5) + (t >= c6) + (t >= c7);
        if (seg != curseg) {               // block-uniform branch
            if (curseg >= 0) {
                atomicAdd(&ssum[curseg * D_DIM + dbase + 0], a0);
                atomicAdd(&ssum[curseg * D_DIM + dbase + 1], a1);
                atomicAdd(&ssum[curseg * D_DIM + dbase + 2], a2);
                atomicAdd(&ssum[curseg * D_DIM + dbase + 3], a3);
                touched[curseg] = 1;
            }
            curseg = seg;
            a0 = a1 = a2 = a3 = 0.f;
        }
        float4 v = x[(size_t)t * (HD / 4) + tid];
        a0 += v.x; a1 += v.y; a2 += v.z; a3 += v.w;
    }
    if (curseg >= 0) {
        atomicAdd(&ssum[curseg * D_DIM + dbase + 0], a0);
        atomicAdd(&ssum[curseg * D_DIM + dbase + 1], a1);
        atomicAdd(&ssum[curseg * D_DIM + dbase + 2], a2);
        atomicAdd(&ssum[curseg * D_DIM + dbase + 3], a3);
        touched[curseg] = 1;
    }
    __syncthreads();

    for (int s = 0; s < B_SEG; s++) {
        if (touched[s]) {
            for (int i = tid; i < D_DIM; i += 256)
                atomicAdd(&g_sums[s * D_DIM + i], ssum[s * D_DIM + i]);
        }
    }
}

// ---------------------------------------------------------------------------
// Grid barrier (counters zeroed by zero_kernel each replay; NB blocks resident)
// ---------------------------------------------------------------------------
__device__ __forceinline__ void gbar(int idx) {
    __syncthreads();
    __threadfence();
    if (threadIdx.x == 0) {
        unsigned a = atomicAdd(&g_bar[idx], 1u) + 1u;
        if (a < NB) {
            volatile unsigned* p = &g_bar[idx];
            while (*p < NB) { __nanosleep(32); }
        }
    }
    __syncthreads();
    __threadfence();
}

// ---------------------------------------------------------------------------
// K2: fused MLP.  NB=16 blocks x 256 threads = 4096 threads.
// Deterministic split-K partials (no atomics). 4 grid barriers.
// ---------------------------------------------------------------------------
__global__ __launch_bounds__(256) void fused_mlp_kernel(
    const int*   __restrict__ cu,
    const float* __restrict__ w1, const float* __restrict__ b1,
    const float* __restrict__ w2, const float* __restrict__ b2,
    const float* __restrict__ w3, const float* __restrict__ b3,
    const float* __restrict__ w4, const float* __restrict__ b4,
    const float* __restrict__ w5, const float* __restrict__ b5,
    float* __restrict__ out)
{
    __shared__ float sm[2048];   // aliased per stage (max: L5 needs 2048)

    const int tid = threadIdx.x;
    const int bid = blockIdx.x;
    const int gt  = bid * 256 + tid;

    // ===== L1: pooled(8x128) -> h1(8x1024), silu ============================
    // Thread: col j = gt & 1023, batch pair p = gt >> 10 (b0 = 2p, b0+1).
    {
        float* s_pool = sm;   // [8][128]
        for (int i = tid; i < B_SEG * D_DIM; i += 256) {
            const int b = i >> 7;
            const int cnt = cu[b + 1] - cu[b];
            const float c = (float)(cnt > 1 ? cnt : 1);
            s_pool[i] = g_sums[i] * (1.0f / (8.0f * c));
        }
        __syncthreads();

        const int j  = gt & 1023;
        const int b0 = (gt >> 10) << 1;     // 0,2,4,6
        const float* p0 = &s_pool[b0 * 128];
        const float* p1 = &s_pool[b0 * 128 + 128];
        float acc0 = b1[j], acc1 = b1[j];
        #pragma unroll 8
        for (int k = 0; k < 128; k++) {
            const float w = w1[k * 1024 + j];
            acc0 += p0[k] * w;
            acc1 += p1[k] * w;
        }
        g_h1[(b0 + 0) * 1024 + j] = silu_f(acc0);
        g_h1[(b0 + 1) * 1024 + j] = silu_f(acc1);
    }
    gbar(0);

    // ===== L2: h1(8x1024) -> partials(16 x 8 x 256), no act ================
    // Block = k-chunk of 64; thread = col j = tid; all 8 batches.
    {
        float* s_in = sm;   // [8][64]
        __syncthreads();
        for (int i = tid; i < B_SEG * 64; i += 256) {
            const int b = i >> 6;
            const int k = i & 63;
            s_in[i] = g_h1[b * 1024 + bid * 64 + k];
        }
        __syncthreads();

        const int j = tid;
        float acc[B_SEG];
        #pragma unroll
        for (int b = 0; b < B_SEG; b++) acc[b] = 0.0f;
        #pragma unroll 4
        for (int k = 0; k < 64; k++) {
            const float w = w2[(bid * 64 + k) * 256 + j];
            #pragma unroll
            for (int b = 0; b < B_SEG; b++)
                acc[b] += s_in[b * 64 + k] * w;
        }
        #pragma unroll
        for (int b = 0; b < B_SEG; b++)
            g_p2[(bid * B_SEG + b) * 256 + j] = acc[b];
    }
    gbar(1);

    // ===== L3: h2(8x256) -> h3(8x512), silu ================================
    // Block covers batch b = bid>>1, cols j = (bid&1)*256 + tid.
    {
        float* s_h2 = sm;   // [256]
        const int b = bid >> 1;
        __syncthreads();
        {
            const int k = tid;
            float v = b2[k];
            #pragma unroll
            for (int c = 0; c < NB; c++)
                v += g_p2[(c * B_SEG + b) * 256 + k];
            s_h2[k] = v;
        }
        __syncthreads();

        const int j = ((bid & 1) << 8) + tid;
        float acc = b3[j];
        #pragma unroll 8
        for (int k = 0; k < 256; k++)
            acc += s_h2[k] * w3[k * 512 + j];
        g_h3[b * 512 + j] = silu_f(acc);
    }
    gbar(2);

    // ===== L4: h3(8x512) -> partials(16 x 8 x 128), act deferred ===========
    // Block = k-chunk of 32; thread: j = tid&127, batch half bh = tid>>7 (4 b each).
    {
        float* s_in = sm;   // [8][32]
        __syncthreads();
        for (int i = tid; i < B_SEG * 32; i += 256) {
            const int b = i >> 5;
            const int k = i & 31;
            s_in[i] = g_h3[b * 512 + bid * 32 + k];
        }
        __syncthreads();

        const int j  = tid & 127;
        const int bh = tid >> 7;          // 0 or 1
        float acc[4];
        #pragma unroll
        for (int i = 0; i < 4; i++) acc[i] = 0.0f;
        #pragma unroll 4
        for (int k = 0; k < 32; k++) {
            const float w = w4[(bid * 32 + k) * 128 + j];
            #pragma unroll
            for (int i = 0; i < 4; i++)
                acc[i] += s_in[(bh * 4 + i) * 32 + k] * w;
        }
        #pragma unroll
        for (int i = 0; i < 4; i++)
            g_p4[(bid * B_SEG + bh * 4 + i) * 128 + j] = acc[i];
    }
    gbar(3);

    // ===== L5 (block 0 only): logits + hard routing ========================
    if (bid == 0) {
        float* sred0 = sm;          // [8][128]
        float* sred1 = sm + 1024;   // [8][128]
        const int k  = tid & 127;
        const int bh = tid >> 7;    // batches {bh, bh+2, bh+4, bh+6}
        const float wa = w5[k * 2 + 0];
        const float wb = w5[k * 2 + 1];
        const float bias4 = b4[k];

        __syncthreads();
        #pragma unroll
        for (int i = 0; i < 4; i++) {
            const int b = bh + 2 * i;
            float v = bias4;
            #pragma unroll
            for (int c = 0; c < NB; c++)
                v += g_p4[(c * B_SEG + b) * 128 + k];
            const float s = silu_f(v);
            sred0[b * 128 + k] = s * wa;
            sred1[b * 128 + k] = s * wb;
        }
        __syncthreads();

        for (int off = 64; off >= 1; off >>= 1) {
            if (k < off) {
                #pragma unroll
                for (int i = 0; i < 4; i++) {
                    const int b = bh + 2 * i;
                    sred0[b * 128 + k] += sred0[b * 128 + k + off];
                    sred1[b * 128 + k] += sred1[b * 128 + k + off];
                }
            }
            __syncthreads();
        }

        if (k == 0) {
            const float bz0 = b5[0], bz1 = b5[1];
            #pragma unroll
            for (int i = 0; i < 4; i++) {
                const int b = bh + 2 * i;
                const float l0 = sred0[b * 128] + bz0;
                const float l1 = sred1[b * 128] + bz1;
                const float z  = (l1 > l0) ? 1.0f : 0.0f;
                #pragma unroll
                for (int h = 0; h < H_HEAD; h++)
                    out[b * H_HEAD + h] = z;
            }
        }
    }
}

// ---------------------------------------------------------------------------
// Launch: 3 graph nodes total
// ---------------------------------------------------------------------------
extern "C" void kernel_launch(void* const* d_in, const int* in_sizes, int n_in,
                              void* d_out, int out_size)
{
    const float* x  = (const float*)d_in[0];
    const int*   cu = (const int*)  d_in[1];
    const float* w1 = (const float*)d_in[2];
    const float* b1 = (const float*)d_in[3];
    const float* w2 = (const float*)d_in[4];
    const float* b2 = (const float*)d_in[5];
    const float* w3 = (const float*)d_in[6];
    const float* b3 = (const float*)d_in[7];
    const float* w4 = (const float*)d_in[8];
    const float* b4 = (const float*)d_in[9];
    const float* w5 = (const float*)d_in[10];
    const float* b5 = (const float*)d_in[11];
    float* out = (float*)d_out;

    zero_kernel<<<4, 256>>>();
    segsum_kernel<<<SEG_BLOCKS, 256>>>((const float4*)x, cu);
    fused_mlp_kernel<<<NB, 256>>>(cu, w1, b1, w2, b2, w3, b3, w4, b4, w5, b5, out);
}

// round 5
// speedup vs baseline: 2.3176x; 1.3615x over previous
#include <cuda_runtime.h>
#include <cuda_bf16.h>

// Problem constants
#define T_TOK   32768
#define B_SEG   8
#define H_HEAD  8
#define D_DIM   128
#define HD      (H_HEAD * D_DIM)   // 1024 floats per token row

// Fused-kernel geometry
#define NBLK    512                // total blocks (all do segsum)
#define TPB     256
#define TOKS    (T_TOK / NBLK)     // 64 tokens per block
#define NB_MLP  16                 // blocks that continue into the MLP

// Scratch (device globals — zero-initialized at module load; g_sums and g_bar
// are restored to zero by block 0 at the END of every call, so the entry
// invariant (all zero) holds on every graph replay deterministically).
__device__ float    g_sums[B_SEG * D_DIM];
__device__ float    g_h1[B_SEG * 1024];
__device__ float    g_p2[NB_MLP * B_SEG * 256];
__device__ float    g_h3[B_SEG * 512];
__device__ float    g_p4[NB_MLP * B_SEG * 128];
__device__ unsigned g_bar[5];

__device__ __forceinline__ float silu_f(float x) {
    return x / (1.0f + __expf(-x));
}

// Arrive: make this block's global writes visible, then count in.
__device__ __forceinline__ void bar_arrive(int i) {
    __threadfence();
    __syncthreads();
    if (threadIdx.x == 0) atomicAdd(&g_bar[i], 1u);
}
// Wait until all NBLK blocks have arrived at counter i.
__device__ __forceinline__ void bar_wait(int i) {
    if (threadIdx.x == 0) {
        volatile unsigned* p = &g_bar[i];
        while (*p < NBLK) __nanosleep(64);
    }
    __syncthreads();
    __threadfence();
}

// ---------------------------------------------------------------------------
// Single fused kernel: segment+head sum  ->  5-layer MLP  ->  hard routing
// ---------------------------------------------------------------------------
__global__ __launch_bounds__(TPB) void fused_all_kernel(
    const float4* __restrict__ x, const int* __restrict__ cu,
    const float* __restrict__ w1, const float* __restrict__ b1,
    const float* __restrict__ w2, const float* __restrict__ b2,
    const float* __restrict__ w3, const float* __restrict__ b3,
    const float* __restrict__ w4, const float* __restrict__ b4,
    const float* __restrict__ w5, const float* __restrict__ b5,
    float* __restrict__ out)
{
    __shared__ float sm[2048];          // aliased per phase (max: L5 = 2048)
    __shared__ int   touched[B_SEG];

    const int tid = threadIdx.x;
    const int bid = blockIdx.x;

    // ======================= Phase A: segsum ===============================
    // g_sums[b][d] = sum_{t in seg b} sum_h x[t,h,d].  Block owns 64 rows.
    {
        float* ssum = sm;               // [8][128]
        for (int i = tid; i < B_SEG * D_DIM; i += TPB) ssum[i] = 0.0f;
        if (tid < B_SEG) touched[tid] = 0;
        __syncthreads();

        const int c1 = cu[1], c2 = cu[2], c3 = cu[3], c4 = cu[4];
        const int c5 = cu[5], c6 = cu[6], c7 = cu[7];

        const int t0    = bid * TOKS;
        const int dbase = (4 * tid) & (D_DIM - 1);

        float a0 = 0.f, a1 = 0.f, a2 = 0.f, a3 = 0.f;
        int curseg = -1;

        #pragma unroll 8
        for (int tt = 0; tt < TOKS; tt++) {
            const int t = t0 + tt;
            // seg = #inner boundaries <= t (matches searchsorted 'right' - 1,
            // incl. duplicate-boundary / empty-segment cases)
            int seg = (t >= c1) + (t >= c2) + (t >= c3) + (t >= c4)
                    + (t >= c5) + (t >= c6) + (t >= c7);
            if (seg != curseg) {        // block-uniform branch
                if (curseg >= 0) {
                    atomicAdd(&ssum[curseg * D_DIM + dbase + 0], a0);
                    atomicAdd(&ssum[curseg * D_DIM + dbase + 1], a1);
                    atomicAdd(&ssum[curseg * D_DIM + dbase + 2], a2);
                    atomicAdd(&ssum[curseg * D_DIM + dbase + 3], a3);
                    touched[curseg] = 1;
                }
                curseg = seg;
                a0 = a1 = a2 = a3 = 0.f;
            }
            // streaming load: evict-first so MLP weights stay L2-resident
            float4 v = __ldcs(&x[(size_t)t * (HD / 4) + tid]);
            a0 += v.x; a1 += v.y; a2 += v.z; a3 += v.w;
        }
        if (curseg >= 0) {
            atomicAdd(&ssum[curseg * D_DIM + dbase + 0], a0);
            atomicAdd(&ssum[curseg * D_DIM + dbase + 1], a1);
            atomicAdd(&ssum[curseg * D_DIM + dbase + 2], a2);
            atomicAdd(&ssum[curseg * D_DIM + dbase + 3], a3);
            touched[curseg] = 1;
        }
        __syncthreads();

        for (int s = 0; s < B_SEG; s++) {
            if (touched[s]) {
                for (int i = tid; i < D_DIM; i += TPB)
                    atomicAdd(&g_sums[s * D_DIM + i], ssum[s * D_DIM + i]);
            }
        }
    }

    // ======================= Barrier / early exit ==========================
    if (bid >= NB_MLP) {
        // Arrive at ALL barriers, then leave. Never spins -> no deadlock,
        // SMs drain immediately.
        __threadfence();
        __syncthreads();
        if (tid == 0) {
            atomicAdd(&g_bar[0], 1u);
            atomicAdd(&g_bar[1], 1u);
            atomicAdd(&g_bar[2], 1u);
            atomicAdd(&g_bar[3], 1u);
            atomicAdd(&g_bar[4], 1u);
        }
        return;
    }

    bar_arrive(0);
    bar_wait(0);

    const int gt = bid * TPB + tid;     // 0..4095 over the 16 MLP blocks

    // ===== L1: pooled(8x128) -> h1(8x1024), silu ===========================
    {
        float* s_pool = sm;             // [8][128]
        __syncthreads();
        for (int i = tid; i < B_SEG * D_DIM; i += TPB) {
            const int b = i >> 7;
            const int cnt = cu[b + 1] - cu[b];
            const float c = (float)(cnt > 1 ? cnt : 1);
            s_pool[i] = g_sums[i] * (1.0f / (8.0f * c));
        }
        __syncthreads();

        const int j  = gt & 1023;
        const int b0 = (gt >> 10) << 1;     // 0,2,4,6
        const float* p0 = &s_pool[b0 * 128];
        const float* p1 = &s_pool[b0 * 128 + 128];
        float acc0 = b1[j], acc1 = b1[j];
        #pragma unroll 8
        for (int k = 0; k < 128; k++) {
            const float w = w1[k * 1024 + j];
            acc0 += p0[k] * w;
            acc1 += p1[k] * w;
        }
        g_h1[(b0 + 0) * 1024 + j] = silu_f(acc0);
        g_h1[(b0 + 1) * 1024 + j] = silu_f(acc1);
    }
    bar_arrive(1);
    bar_wait(1);

    // ===== L2: h1(8x1024) -> partials(16 x 8 x 256) ========================
    {
        float* s_in = sm;               // [8][64]
        __syncthreads();
        for (int i = tid; i < B_SEG * 64; i += TPB) {
            const int b = i >> 6;
            const int k = i & 63;
            s_in[i] = g_h1[b * 1024 + bid * 64 + k];
        }
        __syncthreads();

        const int j = tid;
        float acc[B_SEG];
        #pragma unroll
        for (int b = 0; b < B_SEG; b++) acc[b] = 0.0f;
        #pragma unroll 4
        for (int k = 0; k < 64; k++) {
            const float w = w2[(bid * 64 + k) * 256 + j];
            #pragma unroll
            for (int b = 0; b < B_SEG; b++)
                acc[b] += s_in[b * 64 + k] * w;
        }
        #pragma unroll
        for (int b = 0; b < B_SEG; b++)
            g_p2[(bid * B_SEG + b) * 256 + j] = acc[b];
    }
    bar_arrive(2);
    bar_wait(2);

    // ===== L3: h2(8x256) -> h3(8x512), silu ================================
    {
        float* s_h2 = sm;               // [256]
        const int b = bid >> 1;
        __syncthreads();
        {
            const int k = tid;
            float v = b2[k];
            #pragma unroll
            for (int c = 0; c < NB_MLP; c++)
                v += g_p2[(c * B_SEG + b) * 256 + k];
            s_h2[k] = v;
        }
        __syncthreads();

        const int j = ((bid & 1) << 8) + tid;
        float acc = b3[j];
        #pragma unroll 8
        for (int k = 0; k < 256; k++)
            acc += s_h2[k] * w3[k * 512 + j];
        g_h3[b * 512 + j] = silu_f(acc);
    }
    bar_arrive(3);
    bar_wait(3);

    // ===== L4: h3(8x512) -> partials(16 x 8 x 128), silu deferred ==========
    {
        float* s_in = sm;               // [8][32]
        __syncthreads();
        for (int i = tid; i < B_SEG * 32; i += TPB) {
            const int b = i >> 5;
            const int k = i & 31;
            s_in[i] = g_h3[b * 512 + bid * 32 + k];
        }
        __syncthreads();

        const int j  = tid & 127;
        const int bh = tid >> 7;        // 0 or 1
        float acc[4];
        #pragma unroll
        for (int i = 0; i < 4; i++) acc[i] = 0.0f;
        #pragma unroll 4
        for (int k = 0; k < 32; k++) {
            const float w = w4[(bid * 32 + k) * 128 + j];
            #pragma unroll
            for (int i = 0; i < 4; i++)
                acc[i] += s_in[(bh * 4 + i) * 32 + k] * w;
        }
        #pragma unroll
        for (int i = 0; i < 4; i++)
            g_p4[(bid * B_SEG + bh * 4 + i) * 128 + j] = acc[i];
    }
    bar_arrive(4);                      // blocks 1..15 arrive and exit
    if (bid != 0) return;
    bar_wait(4);                        // ONLY block 0 ever waits here

    // ===== L5 (block 0): logits + hard routing =============================
    {
        float* sred0 = sm;              // [8][128]
        float* sred1 = sm + 1024;       // [8][128]
        const int k  = tid & 127;
        const int bh = tid >> 7;        // batches {bh, bh+2, bh+4, bh+6}
        const float wa = w5[k * 2 + 0];
        const float wb = w5[k * 2 + 1];
        const float bias4 = b4[k];

        __syncthreads();
        #pragma unroll
        for (int i = 0; i < 4; i++) {
            const int b = bh + 2 * i;
            float v = bias4;
            #pragma unroll
            for (int c = 0; c < NB_MLP; c++)
                v += g_p4[(c * B_SEG + b) * 128 + k];
            const float s = silu_f(v);
            sred0[b * 128 + k] = s * wa;
            sred1[b * 128 + k] = s * wb;
        }
        __syncthreads();

        for (int off = 64; off >= 1; off >>= 1) {
            if (k < off) {
                #pragma unroll
                for (int i = 0; i < 4; i++) {
                    const int b = bh + 2 * i;
                    sred0[b * 128 + k] += sred0[b * 128 + k + off];
                    sred1[b * 128 + k] += sred1[b * 128 + k + off];
                }
            }
            __syncthreads();
        }

        if (k == 0) {
            const float bz0 = b5[0], bz1 = b5[1];
            #pragma unroll
            for (int i = 0; i < 4; i++) {
                const int b = bh + 2 * i;
                const float l0 = sred0[b * 128] + bz0;
                const float l1 = sred1[b * 128] + bz1;
                const float z  = (l1 > l0) ? 1.0f : 0.0f;
                #pragma unroll
                for (int h = 0; h < H_HEAD; h++)
                    out[b * H_HEAD + h] = z;
            }
        }
    }

    // ===== Restore entry invariants for the next call ======================
    // Safe: every other block has arrived at every barrier (bar4 count hit
    // NBLK), and only block 0 ever spins on bar4 — nobody else is reading
    // g_bar or g_sums anymore.
    __syncthreads();
    for (int i = tid; i < B_SEG * D_DIM; i += TPB) g_sums[i] = 0.0f;
    if (tid < 5) g_bar[tid] = 0u;
}

// ---------------------------------------------------------------------------
// Launch: ONE graph node
// ---------------------------------------------------------------------------
extern "C" void kernel_launch(void* const* d_in, const int* in_sizes, int n_in,
                              void* d_out, int out_size)
{
    const float* x  = (const float*)d_in[0];
    const int*   cu = (const int*)  d_in[1];
    const float* w1 = (const float*)d_in[2];
    const float* b1 = (const float*)d_in[3];
    const float* w2 = (const float*)d_in[4];
    const float* b2 = (const float*)d_in[5];
    const float* w3 = (const float*)d_in[6];
    const float* b3 = (const float*)d_in[7];
    const float* w4 = (const float*)d_in[8];
    const float* b4 = (const float*)d_in[9];
    const float* w5 = (const float*)d_in[10];
    const float* b5 = (const float*)d_in[11];
    float* out = (float*)d_out;

    fused_all_kernel<<<NBLK, TPB>>>((const float4*)x, cu,
                                    w1, b1, w2, b2, w3, b3, w4, b4, w5, b5, out);
}